// round 14
// baseline (speedup 1.0000x reference)
#include <cuda_runtime.h>
#include <cuda_bf16.h>

#define TT 2048
#define CC 1024
#define HH 16
#define HD 64
#define HD2 32
#define KD 8
#define NEGV (-1.0e9f)

// ---------------------------------------------------------------------------
// Scratch (device globals; allocation at runtime is forbidden)
// ---------------------------------------------------------------------------
__device__ float g_xpart[256 * CC];   // per-block column partial sums of x
__device__ float g_xm[CC];            // mean row of x
__device__ float g_ppart[64 * CC];    // per-block partials of (vm @ Wproj)
__device__ float g_qd0[TT];
__device__ float g_kd0[TT];
__device__ int   g_any;
// slow path
__device__ float g_gpartV[128 * CC];  // slow-path vm partial scratch
__device__ float g_q[TT * CC];
__device__ float g_k[TT * CC];
__device__ float g_v[TT * CC];
__device__ float g_y[TT * CC];
__device__ float g_qd[TT * KD];
__device__ float g_kd[TT * KD];
__device__ float g_vm[CC];
__device__ int   g_cnt[TT];
__device__ unsigned g_barc;
__device__ unsigned g_barg;

// ---------------------------------------------------------------------------
// software grid barrier (slow path only; <=128 blocks, co-resident)
// ---------------------------------------------------------------------------
__device__ __forceinline__ void gbar() {
    __syncthreads();
    if (threadIdx.x == 0) {
        unsigned g0 = ((volatile unsigned*)&g_barg)[0];
        __threadfence();
        if (atomicAdd(&g_barc, 1u) == gridDim.x - 1) {
            g_barc = 0u;
            __threadfence();
            atomicAdd(&g_barg, 1u);
        } else {
            while (((volatile unsigned*)&g_barg)[0] == g0) { }
        }
        __threadfence();
    }
    __syncthreads();
}

// ---------------------------------------------------------------------------
// slow-path helpers (exact reference semantics; never taken for Gaussian data)
// ---------------------------------------------------------------------------
__device__ void gemm_tile(const float* __restrict__ A, const float* __restrict__ B,
                          float* __restrict__ C, int bx, int by, float* smbuf) {
    float* As = smbuf;          // 8 x 128
    float* Bs = smbuf + 1024;   // 8 x 128
    int tid = threadIdx.x;
    int ar = tid >> 1, ac = (tid & 1) * 4;
    int br = tid >> 5, bc = (tid & 31) * 4;
    const float* Aptr = A + (by * 128 + ar) * CC + ac;
    const float* Bptr = B + br * CC + bx * 128 + bc;
    __syncthreads();
    float4 aReg = *(const float4*)Aptr;
    float4 bReg = *(const float4*)Bptr;
    float acc[8][8];
    #pragma unroll
    for (int i = 0; i < 8; i++)
        #pragma unroll
        for (int j = 0; j < 8; j++) acc[i][j] = 0.f;
    int ty = tid >> 4, tx = tid & 15;
    int m0 = ty * 4, n0 = tx * 4;
    for (int kt = 0; kt < CC / 8; kt++) {
        As[(ac + 0) * 128 + ar] = aReg.x;
        As[(ac + 1) * 128 + ar] = aReg.y;
        As[(ac + 2) * 128 + ar] = aReg.z;
        As[(ac + 3) * 128 + ar] = aReg.w;
        *(float4*)&Bs[br * 128 + bc] = bReg;
        __syncthreads();
        if (kt < CC / 8 - 1) {
            aReg = *(const float4*)(Aptr + (kt + 1) * 8);
            bReg = *(const float4*)(Bptr + (kt + 1) * 8 * CC);
        }
        #pragma unroll
        for (int kk = 0; kk < 8; kk++) {
            float4 a0 = *(float4*)&As[kk * 128 + m0];
            float4 a1 = *(float4*)&As[kk * 128 + m0 + 64];
            float4 b0 = *(float4*)&Bs[kk * 128 + n0];
            float4 b1 = *(float4*)&Bs[kk * 128 + n0 + 64];
            float arr[8] = {a0.x, a0.y, a0.z, a0.w, a1.x, a1.y, a1.z, a1.w};
            float brr[8] = {b0.x, b0.y, b0.z, b0.w, b1.x, b1.y, b1.z, b1.w};
            #pragma unroll
            for (int i = 0; i < 8; i++)
                #pragma unroll
                for (int j = 0; j < 8; j++) acc[i][j] += arr[i] * brr[j];
        }
        __syncthreads();
    }
    float* Cp = C + (by * 128) * CC + bx * 128;
    #pragma unroll
    for (int i = 0; i < 8; i++) {
        int ri = (i < 4) ? (m0 + i) : (m0 + 64 + i - 4);
        *(float4*)&Cp[ri * CC + n0]      = make_float4(acc[i][0], acc[i][1], acc[i][2], acc[i][3]);
        *(float4*)&Cp[ri * CC + n0 + 64] = make_float4(acc[i][4], acc[i][5], acc[i][6], acc[i][7]);
    }
}

__device__ void attn_q(int q, float* smbuf) {
    int tid = threadIdx.x;
    __syncthreads();
    if (g_cnt[q] == 0) {
        for (int i = tid; i < 256; i += 256)
            *(float4*)&g_y[q * CC + i * 4] = *(const float4*)&g_vm[i * 4];
        return;
    }
    float* sc  = smbuf;          // 2048
    float* red = smbuf + 2048;   // 256
    float* qv  = smbuf + 2304;   // 64
    float* qds = smbuf + 2368;   // 8
    if (tid < 7) qds[tid] = g_qd[q * KD + tid];
    for (int h = 0; h < HH; h++) {
        if (tid < HD) qv[tid] = g_q[q * CC + h * HD + tid];
        __syncthreads();
        float lmax = -3.0e38f;
        for (int k = tid; k < TT; k += 256) {
            float s = NEGV;
            if (k <= q) {
                bool ok = true;
                #pragma unroll
                for (int i = 0; i < 7; i++) ok &= (g_kd[k * KD + i] == qds[i]);
                if (ok) {
                    const float* kp = g_k + k * CC + h * HD;
                    float d = 0.f;
                    #pragma unroll
                    for (int j = 0; j < HD; j++) d += qv[j] * kp[j];
                    s = d * 0.125f;
                }
            }
            sc[k] = s;
            lmax = fmaxf(lmax, s);
        }
        red[tid] = lmax;
        __syncthreads();
        for (int s2 = 128; s2; s2 >>= 1) {
            if (tid < s2) red[tid] = fmaxf(red[tid], red[tid + s2]);
            __syncthreads();
        }
        float m = red[0];
        __syncthreads();
        float lz = 0.f;
        for (int k = tid; k < TT; k += 256) {
            float p = __expf(sc[k] - m);
            sc[k] = p;
            lz += p;
        }
        red[tid] = lz;
        __syncthreads();
        for (int s2 = 128; s2; s2 >>= 1) {
            if (tid < s2) red[tid] += red[tid + s2];
            __syncthreads();
        }
        float Zinv = 1.0f / red[0];
        __syncthreads();
        int d = tid >> 2, sub = tid & 3;
        float accv = 0.f;
        for (int k = sub; k < TT; k += 4) accv += sc[k] * g_v[k * CC + h * HD + d];
        accv += __shfl_xor_sync(0xffffffffu, accv, 1);
        accv += __shfl_xor_sync(0xffffffffu, accv, 2);
        if (sub == 0) g_y[q * CC + h * HD + d] = accv * Zinv;
        __syncthreads();
    }
}

// ===========================================================================
// Node A: x-pass -> 256 column partials + qd0/kd0. grid 256, 8 rows/block.
// ===========================================================================
__global__ void __launch_bounds__(256) k_scan(const float* __restrict__ x,
                                              const float* __restrict__ Wdq,
                                              const float* __restrict__ Wdk) {
    __shared__ float wq0[CC];
    __shared__ float wk0[CC];
    __shared__ float sdq[8][8];
    __shared__ float sdk[8][8];
    int tid = threadIdx.x;
    int r0 = blockIdx.x * 8;
    for (int i = tid; i < CC; i += 256) {
        wq0[i] = Wdq[i * KD];
        wk0[i] = Wdk[i * KD];
    }
    if (blockIdx.x == 0 && tid == 0) g_any = 0;
    __syncthreads();
    int c4 = tid * 4;
    float4 wq4 = *(const float4*)&wq0[c4];
    float4 wk4 = *(const float4*)&wk0[c4];
    float4 cs = make_float4(0.f, 0.f, 0.f, 0.f);
    float dq[8], dk[8];
    #pragma unroll
    for (int r = 0; r < 8; r++) {
        float4 v = *(const float4*)&x[(r0 + r) * CC + c4];
        cs.x += v.x; cs.y += v.y; cs.z += v.z; cs.w += v.w;
        dq[r] = v.x * wq4.x + v.y * wq4.y + v.z * wq4.z + v.w * wq4.w;
        dk[r] = v.x * wk4.x + v.y * wk4.y + v.z * wk4.z + v.w * wk4.w;
    }
    int w = tid >> 5, l = tid & 31;
    #pragma unroll
    for (int r = 0; r < 8; r++) {
        float a = dq[r], b = dk[r];
        #pragma unroll
        for (int o = 16; o; o >>= 1) {
            a += __shfl_xor_sync(0xffffffffu, a, o);
            b += __shfl_xor_sync(0xffffffffu, b, o);
        }
        if (l == 0) { sdq[r][w] = a; sdk[r][w] = b; }
    }
    __syncthreads();
    if (tid < 8) {
        float s = 0.f;
        #pragma unroll
        for (int j = 0; j < 8; j++) s += sdq[tid][j];
        g_qd0[r0 + tid] = s;
    } else if (tid < 16) {
        float s = 0.f;
        #pragma unroll
        for (int j = 0; j < 8; j++) s += sdk[tid - 8][j];
        g_kd0[r0 + tid - 8] = s;
    }
    *(float4*)&g_xpart[blockIdx.x * CC + c4] = cs;
    cudaTriggerProgrammaticLaunchCompletion();
}

// ===========================================================================
// Node B: coalesced partial reduce -> g_xm (blocks 0..31, 32 cols each)
//         + collision check (blocks 32..95).
// ===========================================================================
__global__ void __launch_bounds__(256) k_mid() {
    cudaGridDependencySynchronize();
    int tid = threadIdx.x;
    if (blockIdx.x < 32) {
        __shared__ float red[8][32];
        int c = tid & 31, g = tid >> 5;
        int c0 = blockIdx.x * 32;
        float s = 0.f;
        #pragma unroll
        for (int m = 0; m < 32; m++)
            s += g_xpart[(g + m * 8) * CC + c0 + c];   // warp: 128B line per p
        red[g][c] = s;
        __syncthreads();
        if (tid < 32) {
            float t = 0.f;
            #pragma unroll
            for (int j = 0; j < 8; j++) t += red[j][tid];
            g_xm[c0 + tid] = t * (1.0f / 2048.0f);
        }
    } else {
        // collision check on component-0 projections (necessary condition for
        // any lcp>=7 match): 64 blocks, 32 queries each, 8 threads/query.
        __shared__ float kd0s[TT];
        int cb = blockIdx.x - 32;
        for (int i = tid; i < TT / 4; i += 256)
            ((float4*)kd0s)[i] = ((const float4*)g_kd0)[i];
        __syncthreads();
        int q = cb * 32 + (tid >> 3);
        int sub = tid & 7;
        float qv = g_qd0[q];
        bool found = false;
        for (int k = sub; k <= q; k += 8) found |= (kd0s[k] == qv);
        if (found) atomicOr(&g_any, 1);
    }
    cudaTriggerProgrammaticLaunchCompletion();
}

// ===========================================================================
// Node C: 64 blocks, each computes a 16-entry vm slice (vm = xm @ Wv) and
// multiplies it into Wproj rows [j0, j0+16) -> full-width partial.
// Carries the full slow path when g_any != 0 (G=64, co-resident).
// ===========================================================================
__global__ void __launch_bounds__(256) k_pv(const float* __restrict__ x,
    const float* __restrict__ cosb, const float* __restrict__ sinb,
    const float* __restrict__ Wq, const float* __restrict__ Wk,
    const float* __restrict__ Wv, const float* __restrict__ Wproj,
    const float* __restrict__ Wdq, const float* __restrict__ Wdk,
    float* __restrict__ out)
{
    cudaGridDependencySynchronize();
    __shared__ float smbuf[2376];
    const int tid = threadIdx.x;
    const int bid = blockIdx.x;
    const int G = gridDim.x;

    if (*((volatile int*)&g_any) == 0) {
        float* xms  = smbuf;          // 1024
        float* red  = smbuf + 1024;   // [16][16]
        float* vm16 = smbuf + 1280;   // 16
        *(float4*)&xms[tid * 4] = *(const float4*)&g_xm[tid * 4];
        __syncthreads();
        int c = tid & 15, g = tid >> 4;
        int j0 = bid * 16;
        {
            const float* Wp = Wv + j0 + c;
            float s = 0.f;
            #pragma unroll 16
            for (int i = g * 64; i < g * 64 + 64; i++)
                s += xms[i] * Wp[i * CC];
            red[g * 16 + c] = s;
        }
        __syncthreads();
        if (tid < 16) {
            float t = 0.f;
            #pragma unroll
            for (int j = 0; j < 16; j++) t += red[j * 16 + tid];
            vm16[tid] = t;
        }
        __syncthreads();
        int n = tid * 4;
        float4 acc = make_float4(0.f, 0.f, 0.f, 0.f);
        #pragma unroll
        for (int jj = 0; jj < 16; jj++) {
            float v = vm16[jj];
            float4 w4 = *(const float4*)&Wproj[(j0 + jj) * CC + n];
            acc.x += v * w4.x; acc.y += v * w4.y;
            acc.z += v * w4.z; acc.w += v * w4.w;
        }
        *(float4*)&g_ppart[bid * CC + n] = acc;
        cudaTriggerProgrammaticLaunchCompletion();
        return;
    }

    // ======================= SLOW PATH (general case) =======================
    const int w = tid >> 5, l = tid & 31;
    for (int t = bid; t < TT; t += G) {
        __syncthreads();
        for (int i = tid; i < CC; i += 256) smbuf[i] = x[t * CC + i];
        __syncthreads();
        float sq = 0.f, sk = 0.f;
        for (int i = l; i < CC; i += 32) {
            float xv = smbuf[i];
            sq += xv * Wdq[i * KD + w];
            sk += xv * Wdk[i * KD + w];
        }
        #pragma unroll
        for (int o = 16; o; o >>= 1) {
            sq += __shfl_xor_sync(0xffffffffu, sq, o);
            sk += __shfl_xor_sync(0xffffffffu, sk, o);
        }
        if (l == 0) { g_qd[t * KD + w] = sq; g_kd[t * KD + w] = sk; }
    }
    gbar();
    for (int q = bid; q < TT; q += G) {
        float q7[7];
        #pragma unroll
        for (int i = 0; i < 7; i++) q7[i] = g_qd[q * KD + i];
        int cnt = 0;
        for (int k = tid; k <= q; k += 256) {
            bool ok = true;
            #pragma unroll
            for (int i = 0; i < 7; i++) ok &= (g_kd[k * KD + i] == q7[i]);
            cnt += ok ? 1 : 0;
        }
        int* red = (int*)smbuf;
        __syncthreads();
        red[tid] = cnt;
        __syncthreads();
        for (int s = 128; s; s >>= 1) {
            if (tid < s) red[tid] += red[tid + s];
            __syncthreads();
        }
        if (tid == 0) g_cnt[q] = red[0];
        __syncthreads();
    }
    gbar();
    for (int j = bid; j < 384; j += G) {
        int z = j >> 7, rem = j & 127;
        const float* B = (z == 0) ? Wq : ((z == 1) ? Wk : Wv);
        float* C = (z == 0) ? g_q : ((z == 1) ? g_k : g_v);
        gemm_tile(x, B, C, rem & 7, rem >> 3, smbuf);
    }
    gbar();
    for (int t = bid; t < TT; t += G) {
        for (int bi = 0; bi < 2; bi++) {
            float* buf = bi ? g_k : g_q;
            #pragma unroll
            for (int it = 0; it < 2; it++) {
                int h = (tid >> 5) + it * 8;
                float* p = buf + t * CC + h * HD;
                float x1 = p[l], x2 = p[l + HD2];
                float c = cosb[t * HD2 + l], s = sinb[t * HD2 + l];
                float o1 = x1 * c - x2 * s, o2 = x1 * s + x2 * c;
                float ss = o1 * o1 + o2 * o2;
                #pragma unroll
                for (int o = 16; o; o >>= 1) ss += __shfl_xor_sync(0xffffffffu, ss, o);
                float r = rsqrtf(ss * (1.0f / 64.0f) + 1e-6f);
                p[l] = o1 * r;
                p[l + HD2] = o2 * r;
            }
        }
    }
    gbar();
    {
        int c = tid * 4;
        float4 s4 = make_float4(0.f, 0.f, 0.f, 0.f);
        for (int t = bid; t < TT; t += G) {
            float4 v = *(const float4*)&g_v[t * CC + c];
            s4.x += v.x; s4.y += v.y; s4.z += v.z; s4.w += v.w;
        }
        *(float4*)&g_gpartV[bid * CC + c] = s4;
    }
    gbar();
    if (bid == 0) {
        for (int c = tid; c < CC; c += 256) {
            float s = 0.f;
            for (int p = 0; p < G; p++) s += g_gpartV[p * CC + c];
            g_vm[c] = s * (1.0f / 2048.0f);
        }
    }
    gbar();
    for (int q = bid; q < TT; q += G) attn_q(q, smbuf);
    gbar();
    for (int j = bid; j < 128; j += G)
        gemm_tile(g_y, Wproj, out, j & 7, j >> 3, smbuf);
    cudaTriggerProgrammaticLaunchCompletion();
}

// ===========================================================================
// Node D: stripe-reduce of 64 row-partials + streaming broadcast.
// grid 1024: stripe = bid & 31 (32 cols), band = bid >> 5 (32 bands x 64 rows).
// ===========================================================================
__global__ void __launch_bounds__(256) k_out(float* __restrict__ out) {
    cudaGridDependencySynchronize();
    if (g_any) return;   // slow path already wrote out
    __shared__ float red[8][32];
    __shared__ float rowv[32];
    int tid = threadIdx.x;
    int c = tid & 31, g = tid >> 5;
    int c0 = (blockIdx.x & 31) * 32;
    int band0 = (blockIdx.x >> 5) * 64;
    float s = 0.f;
    #pragma unroll
    for (int p = g; p < 64; p += 8)
        s += g_ppart[p * CC + c0 + c];       // warp: 128B line per p
    red[g][c] = s;
    __syncthreads();
    if (tid < 32) {
        float t = 0.f;
        #pragma unroll
        for (int j = 0; j < 8; j++) t += red[j][tid];
        rowv[tid] = t;
    }
    __syncthreads();
    // broadcast: (rig = tid>>3, fc = tid&7); 32 rows/iter, 2 iters -> 64 rows.
    int rig = tid >> 3, fc = tid & 7;
    float4 rv = *(const float4*)&rowv[fc * 4];
    #pragma unroll
    for (int m = 0; m < 2; m++) {
        int row = band0 + m * 32 + rig;
        __stcs((float4*)&out[row * CC + c0 + fc * 4], rv);
    }
}

// ---------------------------------------------------------------------------
// launch: 4 graph nodes, B/C/D with PDL (fallback to plain launches).
// ---------------------------------------------------------------------------
extern "C" void kernel_launch(void* const* d_in, const int* in_sizes, int n_in,
                              void* d_out, int out_size) {
    const float* x     = (const float*)d_in[0];
    const float* cosb  = (const float*)d_in[1];
    const float* sinb  = (const float*)d_in[2];
    const float* Wq    = (const float*)d_in[3];
    const float* Wk    = (const float*)d_in[4];
    const float* Wv    = (const float*)d_in[5];
    const float* Wproj = (const float*)d_in[6];
    const float* Wdq   = (const float*)d_in[7];
    const float* Wdk   = (const float*)d_in[8];
    float* out = (float*)d_out;

    k_scan<<<256, 256>>>(x, Wdq, Wdk);

    cudaLaunchAttribute attr[1];
    attr[0].id = cudaLaunchAttributeProgrammaticStreamSerialization;
    attr[0].val.programmaticStreamSerializationAllowed = 1;

    {
        cudaLaunchConfig_t cfg = {};
        cfg.gridDim = dim3(96, 1, 1);
        cfg.blockDim = dim3(256, 1, 1);
        cfg.dynamicSmemBytes = 0;
        cfg.stream = 0;
        cfg.attrs = attr;
        cfg.numAttrs = 1;
        cudaError_t e = cudaLaunchKernelEx(&cfg, k_mid);
        if (e != cudaSuccess) k_mid<<<96, 256>>>();
    }
    {
        cudaLaunchConfig_t cfg = {};
        cfg.gridDim = dim3(64, 1, 1);
        cfg.blockDim = dim3(256, 1, 1);
        cfg.dynamicSmemBytes = 0;
        cfg.stream = 0;
        cfg.attrs = attr;
        cfg.numAttrs = 1;
        cudaError_t e = cudaLaunchKernelEx(&cfg, k_pv, x, cosb, sinb,
                                           Wq, Wk, Wv, Wproj, Wdq, Wdk, out);
        if (e != cudaSuccess)
            k_pv<<<64, 256>>>(x, cosb, sinb, Wq, Wk, Wv, Wproj, Wdq, Wdk, out);
    }
    {
        cudaLaunchConfig_t cfg = {};
        cfg.gridDim = dim3(1024, 1, 1);
        cfg.blockDim = dim3(256, 1, 1);
        cfg.dynamicSmemBytes = 0;
        cfg.stream = 0;
        cfg.attrs = attr;
        cfg.numAttrs = 1;
        cudaError_t e = cudaLaunchKernelEx(&cfg, k_out, out);
        if (e != cudaSuccess) k_out<<<1024, 256>>>(out);
    }
}

// round 15
// speedup vs baseline: 1.1271x; 1.1271x over previous
#include <cuda_runtime.h>
#include <cuda_bf16.h>

#define TT 2048
#define CC 1024
#define HH 16
#define HD 64
#define HD2 32
#define KD 8
#define NEGV (-1.0e9f)

// ---------------------------------------------------------------------------
// Scratch (device globals; allocation at runtime is forbidden)
// ---------------------------------------------------------------------------
__device__ float g_xpart[256 * CC];   // per-block column partial sums of x
__device__ float g_xm[CC];            // mean row of x
__device__ float g_ppart[64 * CC];    // per-block partials of (vm @ Wproj)
__device__ float g_qd0[TT];
__device__ float g_kd0[TT];
__device__ int   g_any;
// slow path
__device__ float g_gpartV[128 * CC];  // slow-path vm partial scratch
__device__ float g_q[TT * CC];
__device__ float g_k[TT * CC];
__device__ float g_v[TT * CC];
__device__ float g_y[TT * CC];
__device__ float g_qd[TT * KD];
__device__ float g_kd[TT * KD];
__device__ float g_vm[CC];
__device__ int   g_cnt[TT];
__device__ unsigned g_barc;
__device__ unsigned g_barg;

// ---------------------------------------------------------------------------
// software grid barrier (slow path only; <=128 blocks, co-resident)
// ---------------------------------------------------------------------------
__device__ __forceinline__ void gbar() {
    __syncthreads();
    if (threadIdx.x == 0) {
        unsigned g0 = ((volatile unsigned*)&g_barg)[0];
        __threadfence();
        if (atomicAdd(&g_barc, 1u) == gridDim.x - 1) {
            g_barc = 0u;
            __threadfence();
            atomicAdd(&g_barg, 1u);
        } else {
            while (((volatile unsigned*)&g_barg)[0] == g0) { }
        }
        __threadfence();
    }
    __syncthreads();
}

// ---------------------------------------------------------------------------
// slow-path helpers (exact reference semantics; never taken for Gaussian data)
// ---------------------------------------------------------------------------
__device__ void gemm_tile(const float* __restrict__ A, const float* __restrict__ B,
                          float* __restrict__ C, int bx, int by, float* smbuf) {
    float* As = smbuf;          // 8 x 128
    float* Bs = smbuf + 1024;   // 8 x 128
    int tid = threadIdx.x;
    int ar = tid >> 1, ac = (tid & 1) * 4;
    int br = tid >> 5, bc = (tid & 31) * 4;
    const float* Aptr = A + (by * 128 + ar) * CC + ac;
    const float* Bptr = B + br * CC + bx * 128 + bc;
    __syncthreads();
    float4 aReg = *(const float4*)Aptr;
    float4 bReg = *(const float4*)Bptr;
    float acc[8][8];
    #pragma unroll
    for (int i = 0; i < 8; i++)
        #pragma unroll
        for (int j = 0; j < 8; j++) acc[i][j] = 0.f;
    int ty = tid >> 4, tx = tid & 15;
    int m0 = ty * 4, n0 = tx * 4;
    for (int kt = 0; kt < CC / 8; kt++) {
        As[(ac + 0) * 128 + ar] = aReg.x;
        As[(ac + 1) * 128 + ar] = aReg.y;
        As[(ac + 2) * 128 + ar] = aReg.z;
        As[(ac + 3) * 128 + ar] = aReg.w;
        *(float4*)&Bs[br * 128 + bc] = bReg;
        __syncthreads();
        if (kt < CC / 8 - 1) {
            aReg = *(const float4*)(Aptr + (kt + 1) * 8);
            bReg = *(const float4*)(Bptr + (kt + 1) * 8 * CC);
        }
        #pragma unroll
        for (int kk = 0; kk < 8; kk++) {
            float4 a0 = *(float4*)&As[kk * 128 + m0];
            float4 a1 = *(float4*)&As[kk * 128 + m0 + 64];
            float4 b0 = *(float4*)&Bs[kk * 128 + n0];
            float4 b1 = *(float4*)&Bs[kk * 128 + n0 + 64];
            float arr[8] = {a0.x, a0.y, a0.z, a0.w, a1.x, a1.y, a1.z, a1.w};
            float brr[8] = {b0.x, b0.y, b0.z, b0.w, b1.x, b1.y, b1.z, b1.w};
            #pragma unroll
            for (int i = 0; i < 8; i++)
                #pragma unroll
                for (int j = 0; j < 8; j++) acc[i][j] += arr[i] * brr[j];
        }
        __syncthreads();
    }
    float* Cp = C + (by * 128) * CC + bx * 128;
    #pragma unroll
    for (int i = 0; i < 8; i++) {
        int ri = (i < 4) ? (m0 + i) : (m0 + 64 + i - 4);
        *(float4*)&Cp[ri * CC + n0]      = make_float4(acc[i][0], acc[i][1], acc[i][2], acc[i][3]);
        *(float4*)&Cp[ri * CC + n0 + 64] = make_float4(acc[i][4], acc[i][5], acc[i][6], acc[i][7]);
    }
}

__device__ void attn_q(int q, float* smbuf) {
    int tid = threadIdx.x;
    __syncthreads();
    if (g_cnt[q] == 0) {
        for (int i = tid; i < 256; i += 256)
            *(float4*)&g_y[q * CC + i * 4] = *(const float4*)&g_vm[i * 4];
        return;
    }
    float* sc  = smbuf;          // 2048
    float* red = smbuf + 2048;   // 256
    float* qv  = smbuf + 2304;   // 64
    float* qds = smbuf + 2368;   // 8
    if (tid < 7) qds[tid] = g_qd[q * KD + tid];
    for (int h = 0; h < HH; h++) {
        if (tid < HD) qv[tid] = g_q[q * CC + h * HD + tid];
        __syncthreads();
        float lmax = -3.0e38f;
        for (int k = tid; k < TT; k += 256) {
            float s = NEGV;
            if (k <= q) {
                bool ok = true;
                #pragma unroll
                for (int i = 0; i < 7; i++) ok &= (g_kd[k * KD + i] == qds[i]);
                if (ok) {
                    const float* kp = g_k + k * CC + h * HD;
                    float d = 0.f;
                    #pragma unroll
                    for (int j = 0; j < HD; j++) d += qv[j] * kp[j];
                    s = d * 0.125f;
                }
            }
            sc[k] = s;
            lmax = fmaxf(lmax, s);
        }
        red[tid] = lmax;
        __syncthreads();
        for (int s2 = 128; s2; s2 >>= 1) {
            if (tid < s2) red[tid] = fmaxf(red[tid], red[tid + s2]);
            __syncthreads();
        }
        float m = red[0];
        __syncthreads();
        float lz = 0.f;
        for (int k = tid; k < TT; k += 256) {
            float p = __expf(sc[k] - m);
            sc[k] = p;
            lz += p;
        }
        red[tid] = lz;
        __syncthreads();
        for (int s2 = 128; s2; s2 >>= 1) {
            if (tid < s2) red[tid] += red[tid + s2];
            __syncthreads();
        }
        float Zinv = 1.0f / red[0];
        __syncthreads();
        int d = tid >> 2, sub = tid & 3;
        float accv = 0.f;
        for (int k = sub; k < TT; k += 4) accv += sc[k] * g_v[k * CC + h * HD + d];
        accv += __shfl_xor_sync(0xffffffffu, accv, 1);
        accv += __shfl_xor_sync(0xffffffffu, accv, 2);
        if (sub == 0) g_y[q * CC + h * HD + d] = accv * Zinv;
        __syncthreads();
    }
}

// ===========================================================================
// Node A: x-pass -> 256 column partials + qd0/kd0. grid 256, 8 rows/block.
// ===========================================================================
__global__ void __launch_bounds__(256) k_scan(const float* __restrict__ x,
                                              const float* __restrict__ Wdq,
                                              const float* __restrict__ Wdk) {
    __shared__ float wq0[CC];
    __shared__ float wk0[CC];
    __shared__ float sdq[8][8];
    __shared__ float sdk[8][8];
    int tid = threadIdx.x;
    int r0 = blockIdx.x * 8;
    for (int i = tid; i < CC; i += 256) {
        wq0[i] = Wdq[i * KD];
        wk0[i] = Wdk[i * KD];
    }
    if (blockIdx.x == 0 && tid == 0) g_any = 0;
    __syncthreads();
    int c4 = tid * 4;
    float4 wq4 = *(const float4*)&wq0[c4];
    float4 wk4 = *(const float4*)&wk0[c4];
    float4 cs = make_float4(0.f, 0.f, 0.f, 0.f);
    float dq[8], dk[8];
    #pragma unroll
    for (int r = 0; r < 8; r++) {
        float4 v = *(const float4*)&x[(r0 + r) * CC + c4];
        cs.x += v.x; cs.y += v.y; cs.z += v.z; cs.w += v.w;
        dq[r] = v.x * wq4.x + v.y * wq4.y + v.z * wq4.z + v.w * wq4.w;
        dk[r] = v.x * wk4.x + v.y * wk4.y + v.z * wk4.z + v.w * wk4.w;
    }
    int w = tid >> 5, l = tid & 31;
    #pragma unroll
    for (int r = 0; r < 8; r++) {
        float a = dq[r], b = dk[r];
        #pragma unroll
        for (int o = 16; o; o >>= 1) {
            a += __shfl_xor_sync(0xffffffffu, a, o);
            b += __shfl_xor_sync(0xffffffffu, b, o);
        }
        if (l == 0) { sdq[r][w] = a; sdk[r][w] = b; }
    }
    __syncthreads();
    if (tid < 8) {
        float s = 0.f;
        #pragma unroll
        for (int j = 0; j < 8; j++) s += sdq[tid][j];
        g_qd0[r0 + tid] = s;
    } else if (tid < 16) {
        float s = 0.f;
        #pragma unroll
        for (int j = 0; j < 8; j++) s += sdk[tid - 8][j];
        g_kd0[r0 + tid - 8] = s;
    }
    *(float4*)&g_xpart[blockIdx.x * CC + c4] = cs;
    cudaTriggerProgrammaticLaunchCompletion();
}

// ===========================================================================
// Node B: coalesced partial reduce -> g_xm (blocks 0..31, 32 cols each)
//         + collision check (blocks 32..95).
// ===========================================================================
__global__ void __launch_bounds__(256) k_mid() {
    cudaGridDependencySynchronize();
    int tid = threadIdx.x;
    if (blockIdx.x < 32) {
        __shared__ float red[8][32];
        int c = tid & 31, g = tid >> 5;
        int c0 = blockIdx.x * 32;
        float s = 0.f;
        #pragma unroll
        for (int m = 0; m < 32; m++)
            s += g_xpart[(g + m * 8) * CC + c0 + c];   // warp: 128B line per p
        red[g][c] = s;
        __syncthreads();
        if (tid < 32) {
            float t = 0.f;
            #pragma unroll
            for (int j = 0; j < 8; j++) t += red[j][tid];
            g_xm[c0 + tid] = t * (1.0f / 2048.0f);
        }
    } else {
        // collision check on component-0 projections (necessary condition for
        // any lcp>=7 match): 64 blocks, 32 queries each, 8 threads/query.
        __shared__ float kd0s[TT];
        int cb = blockIdx.x - 32;
        for (int i = tid; i < TT / 4; i += 256)
            ((float4*)kd0s)[i] = ((const float4*)g_kd0)[i];
        __syncthreads();
        int q = cb * 32 + (tid >> 3);
        int sub = tid & 7;
        float qv = g_qd0[q];
        bool found = false;
        for (int k = sub; k <= q; k += 8) found |= (kd0s[k] == qv);
        if (found) atomicOr(&g_any, 1);
    }
    cudaTriggerProgrammaticLaunchCompletion();
}

// ===========================================================================
// Node C: 64 blocks, each computes a 16-entry vm slice (vm = xm @ Wv) and
// multiplies it into Wproj rows [j0, j0+16) -> full-width partial.
// Carries the full slow path when g_any != 0 (G=gridDim, co-resident).
// ===========================================================================
__global__ void __launch_bounds__(256) k_pv(const float* __restrict__ x,
    const float* __restrict__ cosb, const float* __restrict__ sinb,
    const float* __restrict__ Wq, const float* __restrict__ Wk,
    const float* __restrict__ Wv, const float* __restrict__ Wproj,
    const float* __restrict__ Wdq, const float* __restrict__ Wdk,
    float* __restrict__ out)
{
    cudaGridDependencySynchronize();
    __shared__ float smbuf[2376];
    const int tid = threadIdx.x;
    const int bid = blockIdx.x;
    const int G = gridDim.x;

    if (*((volatile int*)&g_any) == 0) {
        float* xms  = smbuf;          // 1024
        float* red  = smbuf + 1024;   // [16][16]
        float* vm16 = smbuf + 1280;   // 16
        *(float4*)&xms[tid * 4] = *(const float4*)&g_xm[tid * 4];
        __syncthreads();
        int c = tid & 15, g = tid >> 4;
        int j0 = bid * 16;
        {
            const float* Wp = Wv + j0 + c;
            float s = 0.f;
            #pragma unroll 16
            for (int i = g * 64; i < g * 64 + 64; i++)
                s += xms[i] * Wp[i * CC];
            red[g * 16 + c] = s;
        }
        __syncthreads();
        if (tid < 16) {
            float t = 0.f;
            #pragma unroll
            for (int j = 0; j < 16; j++) t += red[j * 16 + tid];
            vm16[tid] = t;
        }
        __syncthreads();
        int n = tid * 4;
        float4 acc = make_float4(0.f, 0.f, 0.f, 0.f);
        #pragma unroll
        for (int jj = 0; jj < 16; jj++) {
            float v = vm16[jj];
            float4 w4 = *(const float4*)&Wproj[(j0 + jj) * CC + n];
            acc.x += v * w4.x; acc.y += v * w4.y;
            acc.z += v * w4.z; acc.w += v * w4.w;
        }
        *(float4*)&g_ppart[bid * CC + n] = acc;
        cudaTriggerProgrammaticLaunchCompletion();
        return;
    }

    // ======================= SLOW PATH (general case) =======================
    const int w = tid >> 5, l = tid & 31;
    for (int t = bid; t < TT; t += G) {
        __syncthreads();
        for (int i = tid; i < CC; i += 256) smbuf[i] = x[t * CC + i];
        __syncthreads();
        float sq = 0.f, sk = 0.f;
        for (int i = l; i < CC; i += 32) {
            float xv = smbuf[i];
            sq += xv * Wdq[i * KD + w];
            sk += xv * Wdk[i * KD + w];
        }
        #pragma unroll
        for (int o = 16; o; o >>= 1) {
            sq += __shfl_xor_sync(0xffffffffu, sq, o);
            sk += __shfl_xor_sync(0xffffffffu, sk, o);
        }
        if (l == 0) { g_qd[t * KD + w] = sq; g_kd[t * KD + w] = sk; }
    }
    gbar();
    for (int q = bid; q < TT; q += G) {
        float q7[7];
        #pragma unroll
        for (int i = 0; i < 7; i++) q7[i] = g_qd[q * KD + i];
        int cnt = 0;
        for (int k = tid; k <= q; k += 256) {
            bool ok = true;
            #pragma unroll
            for (int i = 0; i < 7; i++) ok &= (g_kd[k * KD + i] == q7[i]);
            cnt += ok ? 1 : 0;
        }
        int* red = (int*)smbuf;
        __syncthreads();
        red[tid] = cnt;
        __syncthreads();
        for (int s = 128; s; s >>= 1) {
            if (tid < s) red[tid] += red[tid + s];
            __syncthreads();
        }
        if (tid == 0) g_cnt[q] = red[0];
        __syncthreads();
    }
    gbar();
    for (int j = bid; j < 384; j += G) {
        int z = j >> 7, rem = j & 127;
        const float* B = (z == 0) ? Wq : ((z == 1) ? Wk : Wv);
        float* C = (z == 0) ? g_q : ((z == 1) ? g_k : g_v);
        gemm_tile(x, B, C, rem & 7, rem >> 3, smbuf);
    }
    gbar();
    for (int t = bid; t < TT; t += G) {
        for (int bi = 0; bi < 2; bi++) {
            float* buf = bi ? g_k : g_q;
            #pragma unroll
            for (int it = 0; it < 2; it++) {
                int h = (tid >> 5) + it * 8;
                float* p = buf + t * CC + h * HD;
                float x1 = p[l], x2 = p[l + HD2];
                float c = cosb[t * HD2 + l], s = sinb[t * HD2 + l];
                float o1 = x1 * c - x2 * s, o2 = x1 * s + x2 * c;
                float ss = o1 * o1 + o2 * o2;
                #pragma unroll
                for (int o = 16; o; o >>= 1) ss += __shfl_xor_sync(0xffffffffu, ss, o);
                float r = rsqrtf(ss * (1.0f / 64.0f) + 1e-6f);
                p[l] = o1 * r;
                p[l + HD2] = o2 * r;
            }
        }
    }
    gbar();
    {
        int c = tid * 4;
        float4 s4 = make_float4(0.f, 0.f, 0.f, 0.f);
        for (int t = bid; t < TT; t += G) {
            float4 v = *(const float4*)&g_v[t * CC + c];
            s4.x += v.x; s4.y += v.y; s4.z += v.z; s4.w += v.w;
        }
        *(float4*)&g_gpartV[bid * CC + c] = s4;
    }
    gbar();
    if (bid == 0) {
        for (int c = tid; c < CC; c += 256) {
            float s = 0.f;
            for (int p = 0; p < G; p++) s += g_gpartV[p * CC + c];
            g_vm[c] = s * (1.0f / 2048.0f);
        }
    }
    gbar();
    for (int q = bid; q < TT; q += G) attn_q(q, smbuf);
    gbar();
    for (int j = bid; j < 128; j += G)
        gemm_tile(g_y, Wproj, out, j & 7, j >> 3, smbuf);
    cudaTriggerProgrammaticLaunchCompletion();
}

// ===========================================================================
// Node D: stripe-reduce of 64 row-partials (8 KB, coalesced) + broadcast.
// grid 512: stripe = bid & 31 (32 cols), band = bid >> 5 (16 bands x 128 rows).
// Plain (write-back) stores — output stays dirty in L2 across replays.
// ===========================================================================
__global__ void __launch_bounds__(256) k_out(float* __restrict__ out) {
    cudaGridDependencySynchronize();
    if (g_any) return;   // slow path already wrote out
    __shared__ float red[8][32];
    __shared__ float rowv[32];
    int tid = threadIdx.x;
    int c = tid & 31, g = tid >> 5;
    int c0 = (blockIdx.x & 31) * 32;
    int band0 = (blockIdx.x >> 5) * 128;
    float s = 0.f;
    #pragma unroll
    for (int p = g; p < 64; p += 8)
        s += g_ppart[p * CC + c0 + c];       // warp: 128B line per p
    red[g][c] = s;
    __syncthreads();
    if (tid < 32) {
        float t = 0.f;
        #pragma unroll
        for (int j = 0; j < 8; j++) t += red[j][tid];
        rowv[tid] = t;
    }
    __syncthreads();
    int rig = tid >> 3, fc = tid & 7;
    float4 rv = *(const float4*)&rowv[fc * 4];
    #pragma unroll
    for (int m = 0; m < 4; m++) {
        int row = band0 + m * 32 + rig;
        *(float4*)&out[row * CC + c0 + fc * 4] = rv;
    }
}

// ---------------------------------------------------------------------------
// launch: 4 graph nodes, B/C/D with PDL (fallback to plain launches).
// ---------------------------------------------------------------------------
extern "C" void kernel_launch(void* const* d_in, const int* in_sizes, int n_in,
                              void* d_out, int out_size) {
    const float* x     = (const float*)d_in[0];
    const float* cosb  = (const float*)d_in[1];
    const float* sinb  = (const float*)d_in[2];
    const float* Wq    = (const float*)d_in[3];
    const float* Wk    = (const float*)d_in[4];
    const float* Wv    = (const float*)d_in[5];
    const float* Wproj = (const float*)d_in[6];
    const float* Wdq   = (const float*)d_in[7];
    const float* Wdk   = (const float*)d_in[8];
    float* out = (float*)d_out;

    k_scan<<<256, 256>>>(x, Wdq, Wdk);

    cudaLaunchAttribute attr[1];
    attr[0].id = cudaLaunchAttributeProgrammaticStreamSerialization;
    attr[0].val.programmaticStreamSerializationAllowed = 1;

    {
        cudaLaunchConfig_t cfg = {};
        cfg.gridDim = dim3(96, 1, 1);
        cfg.blockDim = dim3(256, 1, 1);
        cfg.dynamicSmemBytes = 0;
        cfg.stream = 0;
        cfg.attrs = attr;
        cfg.numAttrs = 1;
        cudaError_t e = cudaLaunchKernelEx(&cfg, k_mid);
        if (e != cudaSuccess) k_mid<<<96, 256>>>();
    }
    {
        cudaLaunchConfig_t cfg = {};
        cfg.gridDim = dim3(64, 1, 1);
        cfg.blockDim = dim3(256, 1, 1);
        cfg.dynamicSmemBytes = 0;
        cfg.stream = 0;
        cfg.attrs = attr;
        cfg.numAttrs = 1;
        cudaError_t e = cudaLaunchKernelEx(&cfg, k_pv, x, cosb, sinb,
                                           Wq, Wk, Wv, Wproj, Wdq, Wdk, out);
        if (e != cudaSuccess)
            k_pv<<<64, 256>>>(x, cosb, sinb, Wq, Wk, Wv, Wproj, Wdq, Wdk, out);
    }
    {
        cudaLaunchConfig_t cfg = {};
        cfg.gridDim = dim3(512, 1, 1);
        cfg.blockDim = dim3(256, 1, 1);
        cfg.dynamicSmemBytes = 0;
        cfg.stream = 0;
        cfg.attrs = attr;
        cfg.numAttrs = 1;
        cudaError_t e = cudaLaunchKernelEx(&cfg, k_out, out);
        if (e != cudaSuccess) k_out<<<512, 256>>>(out);
    }
}